// round 12
// baseline (speedup 1.0000x reference)
#include <cuda_runtime.h>
#include <cuda_fp16.h>
#include <math.h>
#include <stdint.h>

// ---------------- problem constants ----------------
#define NLAYERS 6
#define Bb      4
#define Ls      1024
#define DM      512
#define DI      1024
#define NH      16
#define HD      64
#define NS      16
#define CONV_DIM 1056
#define DPROJ   2096
#define DPROJ_PAD 2176          // 17 * 128
#define DFF     2048
#define RWS     4096            // B*L rows
#define EPSF    1e-5f
#define NCHK    16              // scan chunks per sequence
#define CHK     64              // Ls / NCHK

// per-layer packed weight segment sizes (elements, PST layout)
#define LW_IN   (DPROJ_PAD * DM)
#define LW_OUT  (DM * DI)
#define LW_F1   (DFF * DM)
#define LW_F2   (DM * DFF)
#define LW_TOT  (LW_IN + LW_OUT + LW_F1 + LW_F2)

// ---------------- scratch (device globals) ----------------
__device__ float g_x  [RWS * DM];
__device__ float g_zx [RWS * DPROJ];
__device__ float g_y  [RWS * DI];
__device__ float g_P  [RWS * NH];                    // inclusive dA products
__device__ float g_S  [Bb * NH * NCHK * HD * NS];    // chunk-local final states
__device__ float g_dAp[Bb * NH * NCHK];              // per-chunk total dA product
__device__ __half g_xn[RWS * DM];
__device__ __half g_yg[RWS * DI];
__device__ __half g_f [RWS * DFF];
__device__ __half g_w [NLAYERS * LW_TOT];

// ---------------- small helpers ----------------
__device__ __forceinline__ float gelu_exact(float v) {
    return 0.5f * v * (1.0f + erff(v * 0.70710678118654752f));
}
__device__ __forceinline__ float silu_f(float v) {
    return v / (1.0f + expf(-v));
}
__device__ __forceinline__ uint32_t smem_u32(const void* p) {
    uint32_t a;
    asm("{ .reg .u64 t; cvta.to.shared.u64 t, %1; cvt.u32.u64 %0, t; }" : "=r"(a) : "l"(p));
    return a;
}

// PST (packed swizzled tile) element index.
__device__ __forceinline__ size_t pst_idx(int row, int col, int Kt) {
    int tile = (row >> 7) * Kt + (col >> 6);
    int r = row & 127;
    int c = col & 63;
    return (size_t)tile * 8192 + (size_t)(r * 64 + ((((c >> 3) ^ (r & 7)) << 3) + (c & 7)));
}

// ---------------- mbarrier ----------------
#define MBAR_INIT(a, c) asm volatile("mbarrier.init.shared.b64 [%0], %1;" :: "r"(a), "r"(c) : "memory")
#define MBAR_EXPECT_TX(a, n) asm volatile("mbarrier.arrive.expect_tx.shared.b64 _, [%0], %1;" :: "r"(a), "r"(n) : "memory")
#define MBAR_WAIT(a, ph) do { \
    uint32_t _m = (a), _p = (ph), _d; \
    asm volatile("{\n\t.reg .pred p;\n\t" \
        "mbarrier.try_wait.parity.acquire.cta.shared::cta.b64 p, [%1], %2;\n\t" \
        "selp.b32 %0, 1, 0, p;\n\t}" : "=r"(_d) : "r"(_m), "r"(_p) : "memory"); \
    if (!_d) { \
        asm volatile("{\n\t.reg .pred P1;\n\tWL_%=:\n\t" \
            "mbarrier.try_wait.parity.acquire.cta.shared::cta.b64 P1, [%0], %1, 0x989680;\n\t" \
            "@P1 bra.uni WD_%=;\n\tbra.uni WL_%=;\n\tWD_%=:\n\t}" \
            :: "r"(_m), "r"(_p) : "memory"); \
    } } while (0)

// ---------------- bulk async copy ----------------
__device__ __forceinline__ void bulk_cp(uint32_t dst, const void* src, uint32_t bytes, uint32_t mbar) {
    asm volatile("cp.async.bulk.shared::cta.global.mbarrier::complete_tx::bytes [%0], [%1], %2, [%3];"
                 :: "r"(dst), "l"(src), "r"(bytes), "r"(mbar) : "memory");
}

// ---------------- mma / ldmatrix ----------------
__device__ __forceinline__ void ldm_x4(uint32_t* r, uint32_t addr) {
    asm volatile("ldmatrix.sync.aligned.m8n8.x4.shared.b16 {%0,%1,%2,%3}, [%4];"
                 : "=r"(r[0]), "=r"(r[1]), "=r"(r[2]), "=r"(r[3]) : "r"(addr));
}
__device__ __forceinline__ void ldm_x2(uint32_t* r, uint32_t addr) {
    asm volatile("ldmatrix.sync.aligned.m8n8.x2.shared.b16 {%0,%1}, [%2];"
                 : "=r"(r[0]), "=r"(r[1]) : "r"(addr));
}
__device__ __forceinline__ void mma16816(float* c, const uint32_t* a, const uint32_t* b) {
    asm volatile("mma.sync.aligned.m16n8k16.row.col.f32.f16.f16.f32 "
                 "{%0,%1,%2,%3},{%4,%5,%6,%7},{%8,%9},{%0,%1,%2,%3};"
                 : "+f"(c[0]), "+f"(c[1]), "+f"(c[2]), "+f"(c[3])
                 : "r"(a[0]), "r"(a[1]), "r"(a[2]), "r"(a[3]), "r"(b[0]), "r"(b[1]));
}

// ---------------- fp16 GEMM: 64x128 CTA tile, 2 CTAs/SM, 3-stage pipeline ------
#define A_TILEB 8192u
#define B_TILEB 16384u
#define STAGEB  24576u
#define CHUNK_TX 24576u
#define NSTAGE  3

template <int EPI>
__global__ __launch_bounds__(256, 2)
void gemm_mma(const __half* __restrict__ A, const __half* __restrict__ B,
              const float* __restrict__ bias, const float* __restrict__ res,
              float* __restrict__ C, __half* __restrict__ Cpst,
              int N, int K, int KtOut)
{
    extern __shared__ char smem_raw[];
    __shared__ __align__(8) uint64_t s_mbar[NSTAGE];
    const uint32_t sbase = smem_u32(smem_raw);
    const uint32_t mb0 = smem_u32(&s_mbar[0]);

    const int tid = threadIdx.x;
    const int wid = tid >> 5;
    const int lane = tid & 31;
    const int m0 = blockIdx.y * 64;
    const int n0 = blockIdx.x * 128;
    const int wm = (wid & 1) * 32;
    const int wn = (wid >> 1) * 32;
    const int grp = lane >> 3;
    const int glr = lane & 7;
    const int Kt  = K >> 6;
    const int nch = Kt;

    if (tid == 0) {
        MBAR_INIT(mb0, 1); MBAR_INIT(mb0 + 8, 1); MBAR_INIT(mb0 + 16, 1);
    }
    __syncthreads();

    auto arm_load = [&](int ci, int st) {
        if (tid == 0) {
            const uint32_t sb = sbase + (uint32_t)st * STAGEB;
            const uint32_t mbar = mb0 + st * 8;
            MBAR_EXPECT_TX(mbar, CHUNK_TX);
            const size_t aT = ((size_t)(m0 >> 7) * Kt + ci) * 8192 + (size_t)((m0 & 64) << 6);
            const size_t bT = ((size_t)(n0 >> 7) * Kt + ci) * 8192;
            bulk_cp(sb,           A + aT, A_TILEB, mbar);
            bulk_cp(sb + A_TILEB, B + bT, B_TILEB, mbar);
        }
    };

    float acc[2][4][4];
#pragma unroll
    for (int i = 0; i < 2; i++)
#pragma unroll
        for (int j = 0; j < 4; j++)
#pragma unroll
            for (int q = 0; q < 4; q++) acc[i][j][q] = 0.f;

    uint32_t a0[2][4], b0[4][2];
    uint32_t a1[2][4], b1[4][2];

    auto ldfrags = [&](uint32_t sb, int kk, uint32_t (*a)[4], uint32_t (*b)[2]) {
        const uint32_t Ab = sb, Bb2 = sb + A_TILEB;
        const int achunk = 2 * kk + (grp >> 1);
        const int arow_b = wm + (grp & 1) * 8 + glr;
#pragma unroll
        for (int mt = 0; mt < 2; mt++) {
            const int r = arow_b + mt * 16;
            const uint32_t off = (uint32_t)r * 128u + (uint32_t)((achunk ^ (r & 7)) << 4);
            ldm_x4(a[mt], Ab + off);
        }
        const int bchunk = 2 * kk + (grp & 1);
        const int brow_b = wn + glr;
#pragma unroll
        for (int nt = 0; nt < 4; nt++) {
            const int r = brow_b + nt * 8;
            const uint32_t off = (uint32_t)r * 128u + (uint32_t)((bchunk ^ (r & 7)) << 4);
            ldm_x2(b[nt], Bb2 + off);
        }
    };

    auto do_mma = [&](uint32_t (*a)[4], uint32_t (*b)[2]) {
#pragma unroll
        for (int mt = 0; mt < 2; mt++)
#pragma unroll
            for (int nt = 0; nt < 4; nt++)
                mma16816(acc[mt][nt], a[mt], b[nt]);
    };

    arm_load(0, 0);
    if (nch > 1) arm_load(1, 1);
    if (nch > 2) arm_load(2, 2);
    int ph[NSTAGE] = {0, 0, 0};
    MBAR_WAIT(mb0, 0); ph[0] = 1;
    ldfrags(sbase, 0, a0, b0);

    int s = 0;
    for (int i = 0; i < nch; i++) {
        const uint32_t sb = sbase + (uint32_t)s * STAGEB;

        ldfrags(sb, 1, a1, b1);
        do_mma(a0, b0);
        ldfrags(sb, 2, a0, b0);
        do_mma(a1, b1);
        ldfrags(sb, 3, a1, b1);
        do_mma(a0, b0);

        __syncthreads();
        if (i + 3 < nch) arm_load(i + 3, s);
        if (i + 1 < nch) {
            const int sn = (s == NSTAGE - 1) ? 0 : s + 1;
            MBAR_WAIT(mb0 + sn * 8, ph[sn]); ph[sn] ^= 1;
            ldfrags(sbase + (uint32_t)sn * STAGEB, 0, a0, b0);
            s = sn;
        }
        do_mma(a1, b1);
    }

    const int rq = lane >> 2;
    const int cq = (lane & 3) << 1;
#pragma unroll
    for (int mt = 0; mt < 2; mt++) {
        const int row0 = m0 + wm + mt * 16 + rq;
        const int row1 = row0 + 8;
#pragma unroll
        for (int nt = 0; nt < 4; nt++) {
            const int col = n0 + wn + nt * 8 + cq;
            if (col >= N) continue;
            float v0 = acc[mt][nt][0], v1 = acc[mt][nt][1];
            float v2 = acc[mt][nt][2], v3 = acc[mt][nt][3];
            if (EPI == 2 || EPI == 3) {
                const float b0f = bias[col], b1f = bias[col + 1];
                v0 += b0f; v1 += b1f; v2 += b0f; v3 += b1f;
            }
            if (EPI == 2) {
                v0 = gelu_exact(v0); v1 = gelu_exact(v1);
                v2 = gelu_exact(v2); v3 = gelu_exact(v3);
            }
            if (EPI == 1 || EPI == 3) {
                const float2 r0 = *(const float2*)(res + (size_t)row0 * N + col);
                const float2 r1 = *(const float2*)(res + (size_t)row1 * N + col);
                v0 += r0.x; v1 += r0.y; v2 += r1.x; v3 += r1.y;
            }
            if (EPI == 2) {
                const size_t e0 = pst_idx(row0, col, KtOut) >> 1;
                const size_t e1 = pst_idx(row1, col, KtOut) >> 1;
                ((__half2*)Cpst)[e0] = __floats2half2_rn(v0, v1);
                ((__half2*)Cpst)[e1] = __floats2half2_rn(v2, v3);
            } else {
                *(float2*)(C + (size_t)row0 * N + col) = make_float2(v0, v1);
                *(float2*)(C + (size_t)row1 * N + col) = make_float2(v2, v3);
            }
        }
    }
}

// ------- weight fp32 -> fp16 PST layout, all layers per launch ----------
__global__ void wconv_pst(const float* __restrict__ src, __half* __restrict__ dst,
                          int Nsrc, int Npad, int K,
                          long long dst_lstride, long long dst_off, int total)
{
    int i = blockIdx.x * blockDim.x + threadIdx.x;
    if (i >= total) return;
    const int gpl = Npad * (K >> 3);
    const int layer = i / gpl;
    const int g = i - layer * gpl;
    const int n = g / (K >> 3);
    const int k = (g - n * (K >> 3)) << 3;

    float4 v0, v1;
    if (n < Nsrc) {
        const float* s = src + (size_t)layer * Nsrc * K + (size_t)n * K + k;
        v0 = *(const float4*)s;
        v1 = *(const float4*)(s + 4);
    } else {
        v0 = make_float4(0.f, 0.f, 0.f, 0.f);
        v1 = v0;
    }
    __half h[8];
    h[0] = __float2half_rn(v0.x); h[1] = __float2half_rn(v0.y);
    h[2] = __float2half_rn(v0.z); h[3] = __float2half_rn(v0.w);
    h[4] = __float2half_rn(v1.x); h[5] = __float2half_rn(v1.y);
    h[6] = __float2half_rn(v1.z); h[7] = __float2half_rn(v1.w);

    const size_t base = (size_t)layer * dst_lstride + dst_off + pst_idx(n, k, K >> 6);
    *(uint4*)(dst + base) = *(uint4*)h;
}

// ---------------- rmsnorm over 512 -> fp16 PST (or fp32 out) --------------
template <bool SPLIT>
__global__ void rmsnorm512_kernel(const float* __restrict__ x, const float* __restrict__ w,
                                  float* __restrict__ out, __half* __restrict__ oh)
{
    const int row = blockIdx.x;
    const int t = threadIdx.x;                 // 128
    float4 v = ((const float4*)(x + (size_t)row * DM))[t];
    float ss = v.x * v.x + v.y * v.y + v.z * v.z + v.w * v.w;
#pragma unroll
    for (int o = 16; o; o >>= 1) ss += __shfl_xor_sync(0xffffffffu, ss, o);
    __shared__ float s[4];
    if ((t & 31) == 0) s[t >> 5] = ss;
    __syncthreads();
    float sc = rsqrtf((s[0] + s[1] + s[2] + s[3]) / (float)DM + EPSF);
    float4 wv = ((const float4*)w)[t];
    float o0 = v.x * sc * wv.x, o1 = v.y * sc * wv.y;
    float o2 = v.z * sc * wv.z, o3 = v.w * sc * wv.w;
    if (SPLIT) {
        const size_t e = pst_idx(row, t * 4, DM >> 6) >> 1;
        ((__half2*)oh)[e + 0] = __floats2half2_rn(o0, o1);
        ((__half2*)oh)[e + 1] = __floats2half2_rn(o2, o3);
    } else {
        ((float4*)(out + (size_t)row * DM))[t] = make_float4(o0, o1, o2, o3);
    }
}

// ------- gated norm: yg = rmsnorm(y * silu(z), gw) -> fp16 PST ------------
__global__ void gatednorm_kernel(const float* __restrict__ y, const float* __restrict__ zx,
                                 const float* __restrict__ gw, __half* __restrict__ oh)
{
    const int row = blockIdx.x;
    const int t = threadIdx.x;                 // 256
    float4 yv = ((const float4*)(y  + (size_t)row * DI))[t];
    float4 zv = ((const float4*)(zx + (size_t)row * DPROJ))[t];
    float4 v;
    v.x = yv.x * silu_f(zv.x); v.y = yv.y * silu_f(zv.y);
    v.z = yv.z * silu_f(zv.z); v.w = yv.w * silu_f(zv.w);
    float ss = v.x * v.x + v.y * v.y + v.z * v.z + v.w * v.w;
#pragma unroll
    for (int o = 16; o; o >>= 1) ss += __shfl_xor_sync(0xffffffffu, ss, o);
    __shared__ float s[8];
    if ((t & 31) == 0) s[t >> 5] = ss;
    __syncthreads();
    float tot = 0.f;
#pragma unroll
    for (int i = 0; i < 8; i++) tot += s[i];
    float sc = rsqrtf(tot / (float)DI + EPSF);
    float4 wv = ((const float4*)gw)[t];
    const size_t e = pst_idx(row, t * 4, DI >> 6) >> 1;
    ((__half2*)oh)[e + 0] = __floats2half2_rn(v.x * sc * wv.x, v.y * sc * wv.y);
    ((__half2*)oh)[e + 1] = __floats2half2_rn(v.z * sc * wv.z, v.w * sc * wv.w);
}

// ------- fused pass 1: conv+SiLU + dt/dA + chunk-local scan ----------------
// grid (NCHK, NH, B), 64 threads
__global__ __launch_bounds__(64)
void scan1_kernel(const float* __restrict__ zx, const float* __restrict__ cw,
                  const float* __restrict__ cb, const float* __restrict__ dtb,
                  const float* __restrict__ Alog, const float* __restrict__ Dh,
                  float* __restrict__ y, float* __restrict__ P,
                  float* __restrict__ S, float* __restrict__ dAprod)
{
    const int c = blockIdx.x;
    const int h = blockIdx.y;
    const int b = blockIdx.z;
    const int p = threadIdx.x;

    __shared__ float Bs[CHK][NS], Cs[CHK][NS], xs[CHK][HD], dAs[CHK], dts[CHK], sPr[CHK];

    const size_t rowbase = (size_t)b * Ls + (size_t)c * CHK;
    const int l0 = c * CHK;

    // conv+SiLU for xBC channel cc (0..CONV_DIM) at local row li
    auto conv_at = [&](int li, int cc) -> float {
        const float* base = zx + (rowbase + li) * DPROJ + DI + cc;
        const float* w4 = cw + cc * 4;
        float acc = cb[cc];
        const int l = l0 + li;
        if (l >= 3) acc = fmaf(base[-3 * DPROJ], w4[0], acc);
        if (l >= 2) acc = fmaf(base[-2 * DPROJ], w4[1], acc);
        if (l >= 1) acc = fmaf(base[-1 * DPROJ], w4[2], acc);
        acc = fmaf(base[0], w4[3], acc);
        return silu_f(acc);
    };

    for (int i = p; i < CHK * NS; i += 64) {
        const int li = i >> 4, n = i & (NS - 1);
        Bs[li][n] = conv_at(li, DI + n);
        Cs[li][n] = conv_at(li, DI + NS + n);
    }
    const int xc = h * HD + p;
    for (int li = 0; li < CHK; li++)
        xs[li][p] = conv_at(li, xc);
    {
        const float A_h = expf(Alog[h]);
        const float dtb_h = dtb[h];
        for (int i = p; i < CHK; i += 64) {
            float v = zx[(rowbase + i) * DPROJ + (DPROJ - NH) + h] + dtb_h;
            float sp = (v > 20.f) ? v : log1pf(expf(v));
            dts[i] = sp;
            dAs[i] = expf(-A_h * sp);
        }
    }
    __syncthreads();

    float st[NS];
#pragma unroll
    for (int n = 0; n < NS; n++) st[n] = 0.f;
    const float Dv = Dh[h];
    float prod = 1.f;

    for (int li = 0; li < CHK; li++) {
        const float xv = xs[li][p];
        const float coeff = dts[li] * xv;
        const float dAv = dAs[li];
        prod *= dAv;
        if (p == 0) sPr[li] = prod;
        float a0 = 0.f, a1 = 0.f, a2 = 0.f, a3 = 0.f;
#pragma unroll
        for (int n = 0; n < NS; n += 4) {
            st[n + 0] = fmaf(st[n + 0], dAv, coeff * Bs[li][n + 0]);
            a0 = fmaf(st[n + 0], Cs[li][n + 0], a0);
            st[n + 1] = fmaf(st[n + 1], dAv, coeff * Bs[li][n + 1]);
            a1 = fmaf(st[n + 1], Cs[li][n + 1], a1);
            st[n + 2] = fmaf(st[n + 2], dAv, coeff * Bs[li][n + 2]);
            a2 = fmaf(st[n + 2], Cs[li][n + 2], a2);
            st[n + 3] = fmaf(st[n + 3], dAv, coeff * Bs[li][n + 3]);
            a3 = fmaf(st[n + 3], Cs[li][n + 3], a3);
        }
        y[(rowbase + li) * DI + h * HD + p] = ((a0 + a1) + (a2 + a3)) + Dv * xv;
    }
    __syncthreads();

    const size_t bh = (size_t)b * NH + h;
    P[bh * Ls + c * CHK + p] = sPr[p];
    const size_t sb = (bh * NCHK + c) * (HD * NS) + (size_t)p * NS;
#pragma unroll
    for (int n = 0; n < NS; n += 4)
        *(float4*)(S + sb + n) = make_float4(st[n], st[n + 1], st[n + 2], st[n + 3]);
    if (p == 0) dAprod[bh * NCHK + c] = prod;
}

// ------- fused pass 2: chunk-combine + correction (grid (NCHK-1) x NH x B) -----
__global__ __launch_bounds__(64)
void scan3_kernel(const float* __restrict__ zx, const float* __restrict__ cw,
                  const float* __restrict__ cb, const float* __restrict__ P,
                  const float* __restrict__ S, const float* __restrict__ dAprod,
                  float* __restrict__ y)
{
    const int c = blockIdx.x + 1;
    const int h = blockIdx.y;
    const int b = blockIdx.z;
    const int p = threadIdx.x;
    const size_t bh = (size_t)b * NH + h;
    const size_t rowbase = (size_t)b * Ls + (size_t)c * CHK;

    __shared__ float Cs[CHK][NS], Ps[CHK];

    // conv+SiLU for C channels (rows here always have l >= 64, no clamping needed)
    for (int i = p; i < CHK * NS; i += 64) {
        const int li = i >> 4, n = i & (NS - 1);
        const int cc = DI + NS + n;
        const float* base = zx + (rowbase + li) * DPROJ + DI + cc;
        const float* w4 = cw + cc * 4;
        float acc = cb[cc];
        acc = fmaf(base[-3 * DPROJ], w4[0], acc);
        acc = fmaf(base[-2 * DPROJ], w4[1], acc);
        acc = fmaf(base[-1 * DPROJ], w4[2], acc);
        acc = fmaf(base[0], w4[3], acc);
        Cs[li][n] = silu_f(acc);
    }
    Ps[p] = P[bh * Ls + c * CHK + p];

    // chunk-combine: H_c = H_{c-1}*dAp_{c-1} + S_{c-1}, H_0 = 0 (replayed locally)
    float H[NS];
#pragma unroll
    for (int n = 0; n < NS; n++) H[n] = 0.f;
    for (int cc2 = 0; cc2 < c; cc2++) {
        const float dp = dAprod[bh * NCHK + cc2];
        const size_t sb = (bh * NCHK + cc2) * (HD * NS) + (size_t)p * NS;
#pragma unroll
        for (int n = 0; n < NS; n += 4) {
            float4 sv = *(const float4*)(S + sb + n);
            H[n + 0] = fmaf(H[n + 0], dp, sv.x);
            H[n + 1] = fmaf(H[n + 1], dp, sv.y);
            H[n + 2] = fmaf(H[n + 2], dp, sv.z);
            H[n + 3] = fmaf(H[n + 3], dp, sv.w);
        }
    }
    __syncthreads();

    for (int li = 0; li < CHK; li++) {
        float d0 = 0.f, d1 = 0.f, d2 = 0.f, d3 = 0.f;
#pragma unroll
        for (int n = 0; n < NS; n += 4) {
            d0 = fmaf(Cs[li][n + 0], H[n + 0], d0);
            d1 = fmaf(Cs[li][n + 1], H[n + 1], d1);
            d2 = fmaf(Cs[li][n + 2], H[n + 2], d2);
            d3 = fmaf(Cs[li][n + 3], H[n + 3], d3);
        }
        const size_t idx = (rowbase + li) * DI + h * HD + p;
        y[idx] += Ps[li] * ((d0 + d1) + (d2 + d3));
    }
}

// ---------------- host orchestration ----------------
extern "C" void kernel_launch(void* const* d_in, const int* in_sizes, int n_in,
                              void* d_out, int out_size)
{
    const float* x_in        = (const float*)d_in[0];
    const float* in_proj_w   = (const float*)d_in[1];
    const float* conv_w      = (const float*)d_in[2];
    const float* conv_b      = (const float*)d_in[3];
    const float* dt_bias     = (const float*)d_in[4];
    const float* A_log       = (const float*)d_in[5];
    const float* D_ssm       = (const float*)d_in[6];
    const float* gnorm_w     = (const float*)d_in[7];
    const float* out_proj_w  = (const float*)d_in[8];
    const float* ffn_w1      = (const float*)d_in[9];
    const float* ffn_b1      = (const float*)d_in[10];
    const float* ffn_w2      = (const float*)d_in[11];
    const float* ffn_b2      = (const float*)d_in[12];
    const float* norm_mamba_w= (const float*)d_in[13];
    const float* norm_ffn_w  = (const float*)d_in[14];
    const float* final_norm_w= (const float*)d_in[15];
    float* out = (float*)d_out;

    float *x, *zx, *y, *Pb, *Sb, *dApb;
    __half *xn, *yg, *f, *w;
    cudaGetSymbolAddress((void**)&x,    g_x);
    cudaGetSymbolAddress((void**)&zx,   g_zx);
    cudaGetSymbolAddress((void**)&y,    g_y);
    cudaGetSymbolAddress((void**)&Pb,   g_P);
    cudaGetSymbolAddress((void**)&Sb,   g_S);
    cudaGetSymbolAddress((void**)&dApb, g_dAp);
    cudaGetSymbolAddress((void**)&xn,   g_xn);
    cudaGetSymbolAddress((void**)&yg,   g_yg);
    cudaGetSymbolAddress((void**)&f,    g_f);
    cudaGetSymbolAddress((void**)&w,    g_w);

    const int DSM = NSTAGE * (int)STAGEB;   // 73728
    cudaFuncSetAttribute(gemm_mma<0>, cudaFuncAttributeMaxDynamicSharedMemorySize, DSM);
    cudaFuncSetAttribute(gemm_mma<1>, cudaFuncAttributeMaxDynamicSharedMemorySize, DSM);
    cudaFuncSetAttribute(gemm_mma<2>, cudaFuncAttributeMaxDynamicSharedMemorySize, DSM);
    cudaFuncSetAttribute(gemm_mma<3>, cudaFuncAttributeMaxDynamicSharedMemorySize, DSM);

    cudaMemcpyAsync(x, x_in, (size_t)RWS * DM * sizeof(float), cudaMemcpyDeviceToDevice);

    // ---- weight conversion to fp16 PST ----
    {
        int tt;
        tt = NLAYERS * DPROJ_PAD * (DM >> 3);
        wconv_pst<<<(tt + 255) / 256, 256>>>(in_proj_w, w,
            DPROJ, DPROJ_PAD, DM, LW_TOT, 0, tt);
        tt = NLAYERS * DM * (DI >> 3);
        wconv_pst<<<(tt + 255) / 256, 256>>>(out_proj_w, w,
            DM, DM, DI, LW_TOT, LW_IN, tt);
        tt = NLAYERS * DFF * (DM >> 3);
        wconv_pst<<<(tt + 255) / 256, 256>>>(ffn_w1, w,
            DFF, DFF, DM, LW_TOT, LW_IN + LW_OUT, tt);
        tt = NLAYERS * DM * (DFF >> 3);
        wconv_pst<<<(tt + 255) / 256, 256>>>(ffn_w2, w,
            DM, DM, DFF, LW_TOT, LW_IN + LW_OUT + LW_F1, tt);
    }

    for (int layer = 0; layer < NLAYERS; layer++) {
        size_t base = (size_t)layer * LW_TOT;
        const __half* wi = w + base;
        const __half* wo = w + base + LW_IN;
        const __half* w1 = w + base + LW_IN + LW_OUT;
        const __half* w2 = w + base + LW_IN + LW_OUT + LW_F1;
        const float* cw  = conv_w  + (size_t)layer * CONV_DIM * 4;
        const float* cb  = conv_b  + (size_t)layer * CONV_DIM;
        const float* dtb = dt_bias + (size_t)layer * NH;
        const float* Al  = A_log   + (size_t)layer * NH;
        const float* Dh  = D_ssm   + (size_t)layer * NH;
        const float* gw  = gnorm_w + (size_t)layer * DI;
        const float* b1  = ffn_b1  + (size_t)layer * DFF;
        const float* b2  = ffn_b2  + (size_t)layer * DM;
        const float* nmw = norm_mamba_w + (size_t)layer * DM;
        const float* nfw = norm_ffn_w   + (size_t)layer * DM;

        // ---- Mamba block ----
        rmsnorm512_kernel<true><<<RWS, 128>>>(x, nmw, nullptr, xn);
        gemm_mma<0><<<dim3(DPROJ_PAD / 128, RWS / 64), 256, DSM>>>(
            xn, wi, nullptr, nullptr, zx, nullptr, DPROJ, DM, 0);
        scan1_kernel<<<dim3(NCHK, NH, Bb), 64>>>(zx, cw, cb, dtb, Al, Dh, y, Pb, Sb, dApb);
        scan3_kernel<<<dim3(NCHK - 1, NH, Bb), 64>>>(zx, cw, cb, Pb, Sb, dApb, y);
        gatednorm_kernel<<<RWS, 256>>>(y, zx, gw, yg);
        gemm_mma<1><<<dim3(DM / 128, RWS / 64), 256, DSM>>>(
            yg, wo, nullptr, x, x, nullptr, DM, DI, 0);

        // ---- FFN block ----
        rmsnorm512_kernel<true><<<RWS, 128>>>(x, nfw, nullptr, xn);
        gemm_mma<2><<<dim3(DFF / 128, RWS / 64), 256, DSM>>>(
            xn, w1, b1, nullptr, nullptr, f, DFF, DM, DFF >> 6);
        gemm_mma<3><<<dim3(DM / 128, RWS / 64), 256, DSM>>>(
            f, w2, b2, x, x, nullptr, DM, DFF, 0);
    }

    rmsnorm512_kernel<false><<<RWS, 128>>>(x, final_norm_w, out, nullptr);
}

// round 13
// speedup vs baseline: 1.0766x; 1.0766x over previous
#include <cuda_runtime.h>
#include <cuda_fp16.h>
#include <math.h>
#include <stdint.h>

// ---------------- problem constants ----------------
#define NLAYERS 6
#define Bb      4
#define Ls      1024
#define DM      512
#define DI      1024
#define NH      16
#define HD      64
#define NS      16
#define CONV_DIM 1056
#define DPROJ   2096
#define DPROJ_PAD 2176          // 17 * 128
#define DFF     2048
#define RWS     4096            // B*L rows
#define EPSF    1e-5f
#define NCHK    16              // scan chunks per sequence
#define CHK     64              // Ls / NCHK

// per-layer packed weight segment sizes (elements, PST layout)
#define LW_IN   (DPROJ_PAD * DM)
#define LW_OUT  (DM * DI)
#define LW_F1   (DFF * DM)
#define LW_F2   (DM * DFF)
#define LW_TOT  (LW_IN + LW_OUT + LW_F1 + LW_F2)

// ---------------- scratch (device globals) ----------------
__device__ float g_x  [RWS * DM];
__device__ float g_zx [RWS * DPROJ];
__device__ float g_bc [RWS * 32];                    // conv+SiLU B/C channels only
__device__ float g_dt [RWS * NH];
__device__ float g_dA [RWS * NH];
__device__ float g_y  [RWS * DI];
__device__ float g_P  [RWS * NH];                    // inclusive dA products
__device__ float g_S  [Bb * NH * NCHK * HD * NS];    // chunk-local final states
__device__ float g_H  [Bb * NH * NCHK * HD * NS];    // corrected chunk-initial states
__device__ float g_dAp[Bb * NH * NCHK];              // per-chunk total dA product
__device__ __half g_xn[RWS * DM];
__device__ __half g_yg[RWS * DI];
__device__ __half g_f [RWS * DFF];
__device__ __half g_w [NLAYERS * LW_TOT];

// ---------------- small helpers ----------------
__device__ __forceinline__ float gelu_exact(float v) {
    return 0.5f * v * (1.0f + erff(v * 0.70710678118654752f));
}
__device__ __forceinline__ float silu_f(float v) {
    return v / (1.0f + expf(-v));
}
__device__ __forceinline__ uint32_t smem_u32(const void* p) {
    uint32_t a;
    asm("{ .reg .u64 t; cvta.to.shared.u64 t, %1; cvt.u32.u64 %0, t; }" : "=r"(a) : "l"(p));
    return a;
}

// PST (packed swizzled tile) element index.
__device__ __forceinline__ size_t pst_idx(int row, int col, int Kt) {
    int tile = (row >> 7) * Kt + (col >> 6);
    int r = row & 127;
    int c = col & 63;
    return (size_t)tile * 8192 + (size_t)(r * 64 + ((((c >> 3) ^ (r & 7)) << 3) + (c & 7)));
}

// ---------------- mbarrier ----------------
#define MBAR_INIT(a, c) asm volatile("mbarrier.init.shared.b64 [%0], %1;" :: "r"(a), "r"(c) : "memory")
#define MBAR_EXPECT_TX(a, n) asm volatile("mbarrier.arrive.expect_tx.shared.b64 _, [%0], %1;" :: "r"(a), "r"(n) : "memory")
#define MBAR_WAIT(a, ph) do { \
    uint32_t _m = (a), _p = (ph), _d; \
    asm volatile("{\n\t.reg .pred p;\n\t" \
        "mbarrier.try_wait.parity.acquire.cta.shared::cta.b64 p, [%1], %2;\n\t" \
        "selp.b32 %0, 1, 0, p;\n\t}" : "=r"(_d) : "r"(_m), "r"(_p) : "memory"); \
    if (!_d) { \
        asm volatile("{\n\t.reg .pred P1;\n\tWL_%=:\n\t" \
            "mbarrier.try_wait.parity.acquire.cta.shared::cta.b64 P1, [%0], %1, 0x989680;\n\t" \
            "@P1 bra.uni WD_%=;\n\tbra.uni WL_%=;\n\tWD_%=:\n\t}" \
            :: "r"(_m), "r"(_p) : "memory"); \
    } } while (0)

// ---------------- bulk async copy ----------------
__device__ __forceinline__ void bulk_cp(uint32_t dst, const void* src, uint32_t bytes, uint32_t mbar) {
    asm volatile("cp.async.bulk.shared::cta.global.mbarrier::complete_tx::bytes [%0], [%1], %2, [%3];"
                 :: "r"(dst), "l"(src), "r"(bytes), "r"(mbar) : "memory");
}

// ---------------- mma / ldmatrix ----------------
__device__ __forceinline__ void ldm_x4(uint32_t* r, uint32_t addr) {
    asm volatile("ldmatrix.sync.aligned.m8n8.x4.shared.b16 {%0,%1,%2,%3}, [%4];"
                 : "=r"(r[0]), "=r"(r[1]), "=r"(r[2]), "=r"(r[3]) : "r"(addr));
}
__device__ __forceinline__ void ldm_x2(uint32_t* r, uint32_t addr) {
    asm volatile("ldmatrix.sync.aligned.m8n8.x2.shared.b16 {%0,%1}, [%2];"
                 : "=r"(r[0]), "=r"(r[1]) : "r"(addr));
}
__device__ __forceinline__ void mma16816(float* c, const uint32_t* a, const uint32_t* b) {
    asm volatile("mma.sync.aligned.m16n8k16.row.col.f32.f16.f16.f32 "
                 "{%0,%1,%2,%3},{%4,%5,%6,%7},{%8,%9},{%0,%1,%2,%3};"
                 : "+f"(c[0]), "+f"(c[1]), "+f"(c[2]), "+f"(c[3])
                 : "r"(a[0]), "r"(a[1]), "r"(a[2]), "r"(a[3]), "r"(b[0]), "r"(b[1]));
}

// ---------------- fp16 GEMM: 64x128 CTA tile, 2 CTAs/SM, 3-stage pipeline ------
#define A_TILEB 8192u
#define B_TILEB 16384u
#define STAGEB  24576u
#define CHUNK_TX 24576u
#define NSTAGE  3

template <int EPI>
__global__ __launch_bounds__(256, 2)
void gemm_mma(const __half* __restrict__ A, const __half* __restrict__ B,
              const float* __restrict__ bias, const float* __restrict__ res,
              float* __restrict__ C, __half* __restrict__ Cpst,
              int N, int K, int KtOut)
{
    extern __shared__ char smem_raw[];
    __shared__ __align__(8) uint64_t s_mbar[NSTAGE];
    const uint32_t sbase = smem_u32(smem_raw);
    const uint32_t mb0 = smem_u32(&s_mbar[0]);

    const int tid = threadIdx.x;
    const int wid = tid >> 5;
    const int lane = tid & 31;
    const int m0 = blockIdx.y * 64;
    const int n0 = blockIdx.x * 128;
    const int wm = (wid & 1) * 32;
    const int wn = (wid >> 1) * 32;
    const int grp = lane >> 3;
    const int glr = lane & 7;
    const int Kt  = K >> 6;
    const int nch = Kt;

    if (tid == 0) {
        MBAR_INIT(mb0, 1); MBAR_INIT(mb0 + 8, 1); MBAR_INIT(mb0 + 16, 1);
    }
    __syncthreads();

    auto arm_load = [&](int ci, int st) {
        if (tid == 0) {
            const uint32_t sb = sbase + (uint32_t)st * STAGEB;
            const uint32_t mbar = mb0 + st * 8;
            MBAR_EXPECT_TX(mbar, CHUNK_TX);
            const size_t aT = ((size_t)(m0 >> 7) * Kt + ci) * 8192 + (size_t)((m0 & 64) << 6);
            const size_t bT = ((size_t)(n0 >> 7) * Kt + ci) * 8192;
            bulk_cp(sb,           A + aT, A_TILEB, mbar);
            bulk_cp(sb + A_TILEB, B + bT, B_TILEB, mbar);
        }
    };

    float acc[2][4][4];
#pragma unroll
    for (int i = 0; i < 2; i++)
#pragma unroll
        for (int j = 0; j < 4; j++)
#pragma unroll
            for (int q = 0; q < 4; q++) acc[i][j][q] = 0.f;

    uint32_t a0[2][4], b0[4][2];
    uint32_t a1[2][4], b1[4][2];

    auto ldfrags = [&](uint32_t sb, int kk, uint32_t (*a)[4], uint32_t (*b)[2]) {
        const uint32_t Ab = sb, Bb2 = sb + A_TILEB;
        const int achunk = 2 * kk + (grp >> 1);
        const int arow_b = wm + (grp & 1) * 8 + glr;
#pragma unroll
        for (int mt = 0; mt < 2; mt++) {
            const int r = arow_b + mt * 16;
            const uint32_t off = (uint32_t)r * 128u + (uint32_t)((achunk ^ (r & 7)) << 4);
            ldm_x4(a[mt], Ab + off);
        }
        const int bchunk = 2 * kk + (grp & 1);
        const int brow_b = wn + glr;
#pragma unroll
        for (int nt = 0; nt < 4; nt++) {
            const int r = brow_b + nt * 8;
            const uint32_t off = (uint32_t)r * 128u + (uint32_t)((bchunk ^ (r & 7)) << 4);
            ldm_x2(b[nt], Bb2 + off);
        }
    };

    auto do_mma = [&](uint32_t (*a)[4], uint32_t (*b)[2]) {
#pragma unroll
        for (int mt = 0; mt < 2; mt++)
#pragma unroll
            for (int nt = 0; nt < 4; nt++)
                mma16816(acc[mt][nt], a[mt], b[nt]);
    };

    arm_load(0, 0);
    if (nch > 1) arm_load(1, 1);
    if (nch > 2) arm_load(2, 2);
    int ph[NSTAGE] = {0, 0, 0};
    MBAR_WAIT(mb0, 0); ph[0] = 1;
    ldfrags(sbase, 0, a0, b0);

    int s = 0;
    for (int i = 0; i < nch; i++) {
        const uint32_t sb = sbase + (uint32_t)s * STAGEB;

        ldfrags(sb, 1, a1, b1);
        do_mma(a0, b0);
        ldfrags(sb, 2, a0, b0);
        do_mma(a1, b1);
        ldfrags(sb, 3, a1, b1);
        do_mma(a0, b0);

        __syncthreads();
        if (i + 3 < nch) arm_load(i + 3, s);
        if (i + 1 < nch) {
            const int sn = (s == NSTAGE - 1) ? 0 : s + 1;
            MBAR_WAIT(mb0 + sn * 8, ph[sn]); ph[sn] ^= 1;
            ldfrags(sbase + (uint32_t)sn * STAGEB, 0, a0, b0);
            s = sn;
        }
        do_mma(a1, b1);
    }

    const int rq = lane >> 2;
    const int cq = (lane & 3) << 1;
#pragma unroll
    for (int mt = 0; mt < 2; mt++) {
        const int row0 = m0 + wm + mt * 16 + rq;
        const int row1 = row0 + 8;
#pragma unroll
        for (int nt = 0; nt < 4; nt++) {
            const int col = n0 + wn + nt * 8 + cq;
            if (col >= N) continue;
            float v0 = acc[mt][nt][0], v1 = acc[mt][nt][1];
            float v2 = acc[mt][nt][2], v3 = acc[mt][nt][3];
            if (EPI == 2 || EPI == 3) {
                const float b0f = bias[col], b1f = bias[col + 1];
                v0 += b0f; v1 += b1f; v2 += b0f; v3 += b1f;
            }
            if (EPI == 2) {
                v0 = gelu_exact(v0); v1 = gelu_exact(v1);
                v2 = gelu_exact(v2); v3 = gelu_exact(v3);
            }
            if (EPI == 1 || EPI == 3) {
                const float2 r0 = *(const float2*)(res + (size_t)row0 * N + col);
                const float2 r1 = *(const float2*)(res + (size_t)row1 * N + col);
                v0 += r0.x; v1 += r0.y; v2 += r1.x; v3 += r1.y;
            }
            if (EPI == 2) {
                const size_t e0 = pst_idx(row0, col, KtOut) >> 1;
                const size_t e1 = pst_idx(row1, col, KtOut) >> 1;
                ((__half2*)Cpst)[e0] = __floats2half2_rn(v0, v1);
                ((__half2*)Cpst)[e1] = __floats2half2_rn(v2, v3);
            } else {
                *(float2*)(C + (size_t)row0 * N + col) = make_float2(v0, v1);
                *(float2*)(C + (size_t)row1 * N + col) = make_float2(v2, v3);
            }
        }
    }
}

// ------- weight fp32 -> fp16 PST layout, all layers per launch ----------
__global__ void wconv_pst(const float* __restrict__ src, __half* __restrict__ dst,
                          int Nsrc, int Npad, int K,
                          long long dst_lstride, long long dst_off, int total)
{
    int i = blockIdx.x * blockDim.x + threadIdx.x;
    if (i >= total) return;
    const int gpl = Npad * (K >> 3);
    const int layer = i / gpl;
    const int g = i - layer * gpl;
    const int n = g / (K >> 3);
    const int k = (g - n * (K >> 3)) << 3;

    float4 v0, v1;
    if (n < Nsrc) {
        const float* s = src + (size_t)layer * Nsrc * K + (size_t)n * K + k;
        v0 = *(const float4*)s;
        v1 = *(const float4*)(s + 4);
    } else {
        v0 = make_float4(0.f, 0.f, 0.f, 0.f);
        v1 = v0;
    }
    __half h[8];
    h[0] = __float2half_rn(v0.x); h[1] = __float2half_rn(v0.y);
    h[2] = __float2half_rn(v0.z); h[3] = __float2half_rn(v0.w);
    h[4] = __float2half_rn(v1.x); h[5] = __float2half_rn(v1.y);
    h[6] = __float2half_rn(v1.z); h[7] = __float2half_rn(v1.w);

    const size_t base = (size_t)layer * dst_lstride + dst_off + pst_idx(n, k, K >> 6);
    *(uint4*)(dst + base) = *(uint4*)h;
}

// ---------------- rmsnorm over 512 -> fp16 PST (or fp32 out) --------------
template <bool SPLIT>
__global__ void rmsnorm512_kernel(const float* __restrict__ x, const float* __restrict__ w,
                                  float* __restrict__ out, __half* __restrict__ oh)
{
    const int row = blockIdx.x;
    const int t = threadIdx.x;                 // 128
    float4 v = ((const float4*)(x + (size_t)row * DM))[t];
    float ss = v.x * v.x + v.y * v.y + v.z * v.z + v.w * v.w;
#pragma unroll
    for (int o = 16; o; o >>= 1) ss += __shfl_xor_sync(0xffffffffu, ss, o);
    __shared__ float s[4];
    if ((t & 31) == 0) s[t >> 5] = ss;
    __syncthreads();
    float sc = rsqrtf((s[0] + s[1] + s[2] + s[3]) / (float)DM + EPSF);
    float4 wv = ((const float4*)w)[t];
    float o0 = v.x * sc * wv.x, o1 = v.y * sc * wv.y;
    float o2 = v.z * sc * wv.z, o3 = v.w * sc * wv.w;
    if (SPLIT) {
        const size_t e = pst_idx(row, t * 4, DM >> 6) >> 1;
        ((__half2*)oh)[e + 0] = __floats2half2_rn(o0, o1);
        ((__half2*)oh)[e + 1] = __floats2half2_rn(o2, o3);
    } else {
        ((float4*)(out + (size_t)row * DM))[t] = make_float4(o0, o1, o2, o3);
    }
}

// ------- gated norm: yg = rmsnorm(y * silu(z), gw) -> fp16 PST ------------
__global__ void gatednorm_kernel(const float* __restrict__ y, const float* __restrict__ zx,
                                 const float* __restrict__ gw, __half* __restrict__ oh)
{
    const int row = blockIdx.x;
    const int t = threadIdx.x;                 // 256
    float4 yv = ((const float4*)(y  + (size_t)row * DI))[t];
    float4 zv = ((const float4*)(zx + (size_t)row * DPROJ))[t];
    float4 v;
    v.x = yv.x * silu_f(zv.x); v.y = yv.y * silu_f(zv.y);
    v.z = yv.z * silu_f(zv.z); v.w = yv.w * silu_f(zv.w);
    float ss = v.x * v.x + v.y * v.y + v.z * v.z + v.w * v.w;
#pragma unroll
    for (int o = 16; o; o >>= 1) ss += __shfl_xor_sync(0xffffffffu, ss, o);
    __shared__ float s[8];
    if ((t & 31) == 0) s[t >> 5] = ss;
    __syncthreads();
    float tot = 0.f;
#pragma unroll
    for (int i = 0; i < 8; i++) tot += s[i];
    float sc = rsqrtf(tot / (float)DI + EPSF);
    float4 wv = ((const float4*)gw)[t];
    const size_t e = pst_idx(row, t * 4, DI >> 6) >> 1;
    ((__half2*)oh)[e + 0] = __floats2half2_rn(v.x * sc * wv.x, v.y * sc * wv.y);
    ((__half2*)oh)[e + 1] = __floats2half2_rn(v.z * sc * wv.z, v.w * sc * wv.w);
}

// ------- conv+SiLU for B/C channels only (32 per row) -> g_bc ----------------
__global__ void convBC_kernel(const float* __restrict__ zx, const float* __restrict__ cw,
                              const float* __restrict__ cb, float* __restrict__ bc)
{
    const int i = blockIdx.x * blockDim.x + threadIdx.x;
    if (i >= RWS * 32) return;
    const int row = i >> 5;
    const int n = i & 31;
    const int cc = DI + n;                 // conv channel
    const int l = row & (Ls - 1);
    const float* base = zx + (size_t)row * DPROJ + DI + cc;
    const float* w4 = cw + cc * 4;
    float acc = cb[cc];
    if (l >= 3) acc = fmaf(base[-3 * DPROJ], w4[0], acc);
    if (l >= 2) acc = fmaf(base[-2 * DPROJ], w4[1], acc);
    if (l >= 1) acc = fmaf(base[-1 * DPROJ], w4[2], acc);
    acc = fmaf(base[0], w4[3], acc);
    bc[i] = silu_f(acc);
}

// ------- dt = softplus(raw + dtb);  dA = exp(-exp(Alog) * dt) -------
__global__ void dtdA_kernel(const float* __restrict__ zx, const float* __restrict__ dtb,
                            const float* __restrict__ Alog,
                            float* __restrict__ dt, float* __restrict__ dA)
{
    const int i = blockIdx.x * blockDim.x + threadIdx.x;
    if (i >= RWS * NH) return;
    const int h = i & (NH - 1);
    const int row = i >> 4;
    float v = zx[(size_t)row * DPROJ + (DPROJ - NH) + h] + dtb[h];
    float sp = (v > 20.f) ? v : log1pf(expf(v));
    dt[i] = sp;
    dA[i] = expf(-expf(Alog[h]) * sp);
}

// ------- pass 1: inline x-conv (vectorized) + chunk-local scan -------------
// grid (NCHK, NH, B), 64 threads
__global__ __launch_bounds__(64)
void scan1_kernel(const float* __restrict__ zx, const float* __restrict__ cw,
                  const float* __restrict__ cb, const float* __restrict__ bc,
                  const float* __restrict__ dtp, const float* __restrict__ dAp,
                  const float* __restrict__ Dh,
                  float* __restrict__ y, float* __restrict__ P,
                  float* __restrict__ S, float* __restrict__ dAprod)
{
    const int c = blockIdx.x;
    const int h = blockIdx.y;
    const int b = blockIdx.z;
    const int p = threadIdx.x;

    __shared__ float Bs[CHK][NS], Cs[CHK][NS], xs[CHK][HD];
    __shared__ float dAs[CHK], dts[CHK], sPr[CHK];
    __shared__ float4 wq[HD];
    __shared__ float cbs[HD];

    const size_t rowbase = (size_t)b * Ls + (size_t)c * CHK;
    const int l0 = c * CHK;
    const int ch0 = h * HD;

    // stage per-channel conv weights + bias
    wq[p] = *(const float4*)(cw + (ch0 + p) * 4);
    cbs[p] = cb[ch0 + p];
    // B/C from precomputed buffer
    for (int i = p; i < CHK * NS; i += 64) {
        const int li = i >> 4, n = i & (NS - 1);
        const float* r = bc + (rowbase + li) * 32;
        Bs[li][n] = r[n];
        Cs[li][n] = r[16 + n];
    }
    for (int i = p; i < CHK; i += 64) {
        const size_t rr = rowbase + i;
        dts[i] = dtp[rr * NH + h];
        dAs[i] = dAp[rr * NH + h];
    }
    __syncthreads();

    // x-conv, vectorized: 16 float4 outputs per thread
#pragma unroll 4
    for (int it = 0; it < 16; it++) {
        const int idx = it * 64 + p;
        const int li = idx >> 4;
        const int q = (idx & 15) << 2;
        const int l = l0 + li;
        const float* zr = zx + (rowbase + li) * DPROJ + DI + ch0 + q;
        const float4 w0 = wq[q], w1 = wq[q + 1], w2 = wq[q + 2], w3 = wq[q + 3];
        float a0 = cbs[q], a1 = cbs[q + 1], a2 = cbs[q + 2], a3 = cbs[q + 3];
        if (l >= 3) {
            float4 v = *(const float4*)(zr - 3 * DPROJ);
            a0 = fmaf(v.x, w0.x, a0); a1 = fmaf(v.y, w1.x, a1);
            a2 = fmaf(v.z, w2.x, a2); a3 = fmaf(v.w, w3.x, a3);
        }
        if (l >= 2) {
            float4 v = *(const float4*)(zr - 2 * DPROJ);
            a0 = fmaf(v.x, w0.y, a0); a1 = fmaf(v.y, w1.y, a1);
            a2 = fmaf(v.z, w2.y, a2); a3 = fmaf(v.w, w3.y, a3);
        }
        if (l >= 1) {
            float4 v = *(const float4*)(zr - DPROJ);
            a0 = fmaf(v.x, w0.z, a0); a1 = fmaf(v.y, w1.z, a1);
            a2 = fmaf(v.z, w2.z, a2); a3 = fmaf(v.w, w3.z, a3);
        }
        {
            float4 v = *(const float4*)zr;
            a0 = fmaf(v.x, w0.w, a0); a1 = fmaf(v.y, w1.w, a1);
            a2 = fmaf(v.z, w2.w, a2); a3 = fmaf(v.w, w3.w, a3);
        }
        *(float4*)(&xs[li][q]) = make_float4(silu_f(a0), silu_f(a1), silu_f(a2), silu_f(a3));
    }
    __syncthreads();

    float st[NS];
#pragma unroll
    for (int n = 0; n < NS; n++) st[n] = 0.f;
    const float Dv = Dh[h];
    float prod = 1.f;

    for (int li = 0; li < CHK; li++) {
        const float xv = xs[li][p];
        const float coeff = dts[li] * xv;
        const float dAv = dAs[li];
        prod *= dAv;
        if (p == 0) sPr[li] = prod;
        float a0 = 0.f, a1 = 0.f, a2 = 0.f, a3 = 0.f;
#pragma unroll
        for (int n = 0; n < NS; n += 4) {
            st[n + 0] = fmaf(st[n + 0], dAv, coeff * Bs[li][n + 0]);
            a0 = fmaf(st[n + 0], Cs[li][n + 0], a0);
            st[n + 1] = fmaf(st[n + 1], dAv, coeff * Bs[li][n + 1]);
            a1 = fmaf(st[n + 1], Cs[li][n + 1], a1);
            st[n + 2] = fmaf(st[n + 2], dAv, coeff * Bs[li][n + 2]);
            a2 = fmaf(st[n + 2], Cs[li][n + 2], a2);
            st[n + 3] = fmaf(st[n + 3], dAv, coeff * Bs[li][n + 3]);
            a3 = fmaf(st[n + 3], Cs[li][n + 3], a3);
        }
        y[(rowbase + li) * DI + h * HD + p] = ((a0 + a1) + (a2 + a3)) + Dv * xv;
    }
    __syncthreads();

    const size_t bh = (size_t)b * NH + h;
    P[bh * Ls + c * CHK + p] = sPr[p];
    const size_t sb = (bh * NCHK + c) * (HD * NS) + (size_t)p * NS;
#pragma unroll
    for (int n = 0; n < NS; n += 4)
        *(float4*)(S + sb + n) = make_float4(st[n], st[n + 1], st[n + 2], st[n + 3]);
    if (p == 0) dAprod[bh * NCHK + c] = prod;
}

// ------- pass 2: sequential chunk-combine (grid NH x B, 64 thr) -------
__global__ __launch_bounds__(64)
void scan2_kernel(const float* __restrict__ S, const float* __restrict__ dAprod,
                  float* __restrict__ Hbuf)
{
    const int h = blockIdx.x;
    const int b = blockIdx.y;
    const int p = threadIdx.x;
    const size_t bh = (size_t)b * NH + h;

    float H[NS];
#pragma unroll
    for (int n = 0; n < NS; n++) H[n] = 0.f;

    for (int c = 1; c < NCHK; c++) {
        const float dp = dAprod[bh * NCHK + (c - 1)];
        const size_t sb = (bh * NCHK + (c - 1)) * (HD * NS) + (size_t)p * NS;
        const size_t hb = (bh * NCHK + c) * (HD * NS) + (size_t)p * NS;
#pragma unroll
        for (int n = 0; n < NS; n += 4) {
            float4 sv = *(const float4*)(S + sb + n);
            H[n + 0] = fmaf(H[n + 0], dp, sv.x);
            H[n + 1] = fmaf(H[n + 1], dp, sv.y);
            H[n + 2] = fmaf(H[n + 2], dp, sv.z);
            H[n + 3] = fmaf(H[n + 3], dp, sv.w);
            *(float4*)(Hbuf + hb + n) = make_float4(H[n], H[n + 1], H[n + 2], H[n + 3]);
        }
    }
}

// ------- pass 3: parallel correction (grid (NCHK-1) x NH x B, 64 thr) -------
__global__ __launch_bounds__(64)
void scan3_kernel(const float* __restrict__ bc, const float* __restrict__ P,
                  const float* __restrict__ Hbuf, float* __restrict__ y)
{
    const int c = blockIdx.x + 1;
    const int h = blockIdx.y;
    const int b = blockIdx.z;
    const int p = threadIdx.x;
    const size_t bh = (size_t)b * NH + h;
    const size_t rowbase = (size_t)b * Ls + (size_t)c * CHK;

    __shared__ float Cs[CHK][NS], Ps[CHK];

    for (int i = p; i < CHK * NS; i += 64) {
        const int li = i >> 4, n = i & (NS - 1);
        Cs[li][n] = bc[(rowbase + li) * 32 + 16 + n];
    }
    Ps[p] = P[bh * Ls + c * CHK + p];

    float H[NS];
    const size_t hb = (bh * NCHK + c) * (HD * NS) + (size_t)p * NS;
#pragma unroll
    for (int n = 0; n < NS; n += 4) {
        float4 hv = *(const float4*)(Hbuf + hb + n);
        H[n] = hv.x; H[n + 1] = hv.y; H[n + 2] = hv.z; H[n + 3] = hv.w;
    }
    __syncthreads();

    for (int li = 0; li < CHK; li++) {
        float d0 = 0.f, d1 = 0.f, d2 = 0.f, d3 = 0.f;
#pragma unroll
        for (int n = 0; n < NS; n += 4) {
            d0 = fmaf(Cs[li][n + 0], H[n + 0], d0);
            d1 = fmaf(Cs[li][n + 1], H[n + 1], d1);
            d2 = fmaf(Cs[li][n + 2], H[n + 2], d2);
            d3 = fmaf(Cs[li][n + 3], H[n + 3], d3);
        }
        const size_t idx = (rowbase + li) * DI + h * HD + p;
        y[idx] += Ps[li] * ((d0 + d1) + (d2 + d3));
    }
}

// ---------------- host orchestration ----------------
extern "C" void kernel_launch(void* const* d_in, const int* in_sizes, int n_in,
                              void* d_out, int out_size)
{
    const float* x_in        = (const float*)d_in[0];
    const float* in_proj_w   = (const float*)d_in[1];
    const float* conv_w      = (const float*)d_in[2];
    const float* conv_b      = (const float*)d_in[3];
    const float* dt_bias     = (const float*)d_in[4];
    const float* A_log       = (const float*)d_in[5];
    const float* D_ssm       = (const float*)d_in[6];
    const float* gnorm_w     = (const float*)d_in[7];
    const float* out_proj_w  = (const float*)d_in[8];
    const float* ffn_w1      = (const float*)d_in[9];
    const float* ffn_b1      = (const float*)d_in[10];
    const float* ffn_w2      = (const float*)d_in[11];
    const float* ffn_b2      = (const float*)d_in[12];
    const float* norm_mamba_w= (const float*)d_in[13];
    const float* norm_ffn_w  = (const float*)d_in[14];
    const float* final_norm_w= (const float*)d_in[15];
    float* out = (float*)d_out;

    float *x, *zx, *bcb, *dt, *dA, *y, *Pb, *Sb, *Hb, *dApb;
    __half *xn, *yg, *f, *w;
    cudaGetSymbolAddress((void**)&x,    g_x);
    cudaGetSymbolAddress((void**)&zx,   g_zx);
    cudaGetSymbolAddress((void**)&bcb,  g_bc);
    cudaGetSymbolAddress((void**)&dt,   g_dt);
    cudaGetSymbolAddress((void**)&dA,   g_dA);
    cudaGetSymbolAddress((void**)&y,    g_y);
    cudaGetSymbolAddress((void**)&Pb,   g_P);
    cudaGetSymbolAddress((void**)&Sb,   g_S);
    cudaGetSymbolAddress((void**)&Hb,   g_H);
    cudaGetSymbolAddress((void**)&dApb, g_dAp);
    cudaGetSymbolAddress((void**)&xn,   g_xn);
    cudaGetSymbolAddress((void**)&yg,   g_yg);
    cudaGetSymbolAddress((void**)&f,    g_f);
    cudaGetSymbolAddress((void**)&w,    g_w);

    const int DSM = NSTAGE * (int)STAGEB;   // 73728
    cudaFuncSetAttribute(gemm_mma<0>, cudaFuncAttributeMaxDynamicSharedMemorySize, DSM);
    cudaFuncSetAttribute(gemm_mma<1>, cudaFuncAttributeMaxDynamicSharedMemorySize, DSM);
    cudaFuncSetAttribute(gemm_mma<2>, cudaFuncAttributeMaxDynamicSharedMemorySize, DSM);
    cudaFuncSetAttribute(gemm_mma<3>, cudaFuncAttributeMaxDynamicSharedMemorySize, DSM);

    cudaMemcpyAsync(x, x_in, (size_t)RWS * DM * sizeof(float), cudaMemcpyDeviceToDevice);

    // ---- weight conversion to fp16 PST ----
    {
        int tt;
        tt = NLAYERS * DPROJ_PAD * (DM >> 3);
        wconv_pst<<<(tt + 255) / 256, 256>>>(in_proj_w, w,
            DPROJ, DPROJ_PAD, DM, LW_TOT, 0, tt);
        tt = NLAYERS * DM * (DI >> 3);
        wconv_pst<<<(tt + 255) / 256, 256>>>(out_proj_w, w,
            DM, DM, DI, LW_TOT, LW_IN, tt);
        tt = NLAYERS * DFF * (DM >> 3);
        wconv_pst<<<(tt + 255) / 256, 256>>>(ffn_w1, w,
            DFF, DFF, DM, LW_TOT, LW_IN + LW_OUT, tt);
        tt = NLAYERS * DM * (DFF >> 3);
        wconv_pst<<<(tt + 255) / 256, 256>>>(ffn_w2, w,
            DM, DM, DFF, LW_TOT, LW_IN + LW_OUT + LW_F1, tt);
    }

    for (int layer = 0; layer < NLAYERS; layer++) {
        size_t base = (size_t)layer * LW_TOT;
        const __half* wi = w + base;
        const __half* wo = w + base + LW_IN;
        const __half* w1 = w + base + LW_IN + LW_OUT;
        const __half* w2 = w + base + LW_IN + LW_OUT + LW_F1;
        const float* cw  = conv_w  + (size_t)layer * CONV_DIM * 4;
        const float* cb  = conv_b  + (size_t)layer * CONV_DIM;
        const float* dtb = dt_bias + (size_t)layer * NH;
        const float* Al  = A_log   + (size_t)layer * NH;
        const float* Dh  = D_ssm   + (size_t)layer * NH;
        const float* gw  = gnorm_w + (size_t)layer * DI;
        const float* b1  = ffn_b1  + (size_t)layer * DFF;
        const float* b2  = ffn_b2  + (size_t)layer * DM;
        const float* nmw = norm_mamba_w + (size_t)layer * DM;
        const float* nfw = norm_ffn_w   + (size_t)layer * DM;

        // ---- Mamba block ----
        rmsnorm512_kernel<true><<<RWS, 128>>>(x, nmw, nullptr, xn);
        gemm_mma<0><<<dim3(DPROJ_PAD / 128, RWS / 64), 256, DSM>>>(
            xn, wi, nullptr, nullptr, zx, nullptr, DPROJ, DM, 0);
        convBC_kernel<<<(RWS * 32 + 255) / 256, 256>>>(zx, cw, cb, bcb);
        dtdA_kernel<<<(RWS * NH + 255) / 256, 256>>>(zx, dtb, Al, dt, dA);
        scan1_kernel<<<dim3(NCHK, NH, Bb), 64>>>(zx, cw, cb, bcb, dt, dA, Dh, y, Pb, Sb, dApb);
        scan2_kernel<<<dim3(NH, Bb), 64>>>(Sb, dApb, Hb);
        scan3_kernel<<<dim3(NCHK - 1, NH, Bb), 64>>>(bcb, Pb, Hb, y);
        gatednorm_kernel<<<RWS, 256>>>(y, zx, gw, yg);
        gemm_mma<1><<<dim3(DM / 128, RWS / 64), 256, DSM>>>(
            yg, wo, nullptr, x, x, nullptr, DM, DI, 0);

        // ---- FFN block ----
        rmsnorm512_kernel<true><<<RWS, 128>>>(x, nfw, nullptr, xn);
        gemm_mma<2><<<dim3(DFF / 128, RWS / 64), 256, DSM>>>(
            xn, w1, b1, nullptr, nullptr, f, DFF, DM, DFF >> 6);
        gemm_mma<3><<<dim3(DM / 128, RWS / 64), 256, DSM>>>(
            f, w2, b2, x, x, nullptr, DM, DFF, 0);
    }

    rmsnorm512_kernel<false><<<RWS, 128>>>(x, final_norm_w, out, nullptr);
}